// round 7
// baseline (speedup 1.0000x reference)
#include <cuda_runtime.h>
#include <cuda_bf16.h>
#include <cuda_fp16.h>
#include <cstdint>

// ---------------------------------------------------------------------------
// CodebookLayer: out[m] = codebook[argmax_c (2*x.c - ||c||^2)]
//
// Round 7: bf16 screen GEMM, BM=BN=128 BK=32, 4 warps with 64x64 warp tiles
// (halved smem traffic per MMA vs R4), 4-stage cp.async; exact fp64 rescore.
// ---------------------------------------------------------------------------

#define MDIM 8192
#define CDIM 8192
#define KDIM 1024

__device__ __half        g_scores[(size_t)MDIM * CDIM];   // 128 MB scratch
__device__ __nv_bfloat16 g_xb [(size_t)MDIM * KDIM];
__device__ __nv_bfloat16 g_cbb[(size_t)CDIM * KDIM];
__device__ float         g_c2[CDIM];

// ---------------- helpers ---------------------------------------------------
__device__ __forceinline__ uint32_t smem_u32(const void* p) {
    uint32_t a;
    asm("{ .reg .u64 t; cvta.to.shared.u64 t, %1; cvt.u32.u64 %0, t; }"
        : "=r"(a) : "l"(p));
    return a;
}
__device__ __forceinline__ void cp16(uint32_t s, const void* g) {
    asm volatile("cp.async.cg.shared.global [%0], [%1], 16;"
                 :: "r"(s), "l"(g) : "memory");
}
__device__ __forceinline__ void ldsm4(uint32_t* r, uint32_t addr) {
    asm volatile("ldmatrix.sync.aligned.m8n8.x4.shared.b16 {%0,%1,%2,%3}, [%4];"
        : "=r"(r[0]), "=r"(r[1]), "=r"(r[2]), "=r"(r[3]) : "r"(addr));
}
__device__ __forceinline__ void mma_bf16(float* d, const uint32_t* a,
                                         uint32_t b0, uint32_t b1) {
    asm volatile(
        "mma.sync.aligned.m16n8k16.row.col.f32.bf16.bf16.f32 "
        "{%0,%1,%2,%3}, {%4,%5,%6,%7}, {%8,%9}, {%0,%1,%2,%3};"
        : "+f"(d[0]), "+f"(d[1]), "+f"(d[2]), "+f"(d[3])
        : "r"(a[0]), "r"(a[1]), "r"(a[2]), "r"(a[3]), "r"(b0), "r"(b1));
}

// ---------------- kernel 0: fp32 -> bf16 ------------------------------------
__global__ void convert_kernel(const float* __restrict__ s,
                               __nv_bfloat16* __restrict__ d, int n) {
    int i = (blockIdx.x * blockDim.x + threadIdx.x) * 4;
    if (i >= n) return;
    float4 v = *reinterpret_cast<const float4*>(s + i);
    __nv_bfloat162 p0 = {__float2bfloat16(v.x), __float2bfloat16(v.y)};
    __nv_bfloat162 p1 = {__float2bfloat16(v.z), __float2bfloat16(v.w)};
    *reinterpret_cast<__nv_bfloat162*>(d + i)     = p0;
    *reinterpret_cast<__nv_bfloat162*>(d + i + 2) = p1;
}

// ---------------- kernel 1: codebook row norms -------------------------------
__global__ void c2_kernel(const float* __restrict__ cb, int C, int K) {
    int row  = blockIdx.x * (blockDim.x >> 5) + (threadIdx.x >> 5);
    int lane = threadIdx.x & 31;
    if (row >= C) return;
    const float4* p = reinterpret_cast<const float4*>(cb + (size_t)row * K);
    float s = 0.f;
    for (int i = lane; i < (K >> 2); i += 32) {
        float4 v = p[i];
        s += v.x * v.x + v.y * v.y + v.z * v.z + v.w * v.w;
    }
    #pragma unroll
    for (int m = 16; m; m >>= 1) s += __shfl_xor_sync(0xffffffffu, s, m);
    if (lane == 0) g_c2[row] = s;
}

// ---------------- kernel 2: bf16 screening GEMM ------------------------------
// BM=BN=128, BK=32 (64B rows), 128 thr = 4 warps (2x2), warp tile 64x64,
// 4-stage cp.async, prefetch distance 3.
#define NSTAGE 4
#define STAGE_BYTES 16384          // A 8KB + B 8KB
#define NS (KDIM / 32)             // 32 k-stages

__global__ __launch_bounds__(128, 2) void screen_gemm() {
    extern __shared__ __align__(128) char smem[];   // 4 * 16 KB
    const uint32_t sb = smem_u32(smem);

    const int t    = threadIdx.x;
    const int lane = t & 31;
    const int wid  = t >> 5;            // 0..3
    const int wm   = wid >> 1;          // 0..1
    const int wn   = wid & 1;           // 0..1
    const int bm   = blockIdx.y * 128;
    const int bn   = blockIdx.x * 128;

    // ---- cp.async mapping: thread t -> row t, 4 chunks of 16B each ----
    uint32_t woff[4];
    #pragma unroll
    for (int j = 0; j < 4; j++)
        woff[j] = t * 64 + (uint32_t)((j ^ ((t >> 1) & 3)) << 4);

    const __nv_bfloat16* pa = g_xb  + (size_t)(bm + t) * KDIM;
    const __nv_bfloat16* pb = g_cbb + (size_t)(bn + t) * KDIM;

    // ---- ldmatrix bases (R4-proven swizzle) ----
    const int rb = lane & 15;
    uint32_t a_sw[4], a_sx[4], b_sw[4], b_sx[4];
    #pragma unroll
    for (int mi = 0; mi < 4; mi++) {
        int row = wm * 64 + mi * 16 + rb;
        a_sw[mi] = row * 64;
        a_sx[mi] = (uint32_t)(((row >> 1) & 3) << 4);
    }
    #pragma unroll
    for (int g = 0; g < 4; g++) {
        int row = wn * 64 + g * 16 + rb;
        b_sw[g] = 8192 + row * 64;
        b_sx[g] = (uint32_t)(((row >> 1) & 3) << 4);
    }

    // ---- prologue: stages 0..2 ----
    #pragma unroll
    for (int s = 0; s < 3; s++) {
        uint32_t so = sb + s * STAGE_BYTES;
        #pragma unroll
        for (int j = 0; j < 4; j++) {
            cp16(so + woff[j],        pa + j * 8);
            cp16(so + 8192 + woff[j], pb + j * 8);
        }
        asm volatile("cp.async.commit_group;" ::: "memory");
        pa += 32; pb += 32;
    }

    float acc[4][8][4];
    #pragma unroll
    for (int i = 0; i < 4; i++)
        #pragma unroll
        for (int j = 0; j < 8; j++)
            #pragma unroll
            for (int k = 0; k < 4; k++) acc[i][j][k] = 0.f;

    for (int s = 0; s < NS; s++) {
        asm volatile("cp.async.wait_group 2;" ::: "memory");
        __syncthreads();

        if (s + 3 < NS) {
            uint32_t so = sb + ((s + 3) & (NSTAGE - 1)) * STAGE_BYTES;
            #pragma unroll
            for (int j = 0; j < 4; j++) {
                cp16(so + woff[j],        pa + j * 8);
                cp16(so + 8192 + woff[j], pb + j * 8);
            }
            pa += 32; pb += 32;
        }
        asm volatile("cp.async.commit_group;" ::: "memory");

        const uint32_t As = sb + (s & (NSTAGE - 1)) * STAGE_BYTES;

        #pragma unroll
        for (int kk = 0; kk < 2; kk++) {
            const uint32_t cx = (uint32_t)(kk * 2 + (lane >> 4)) << 4;
            uint32_t a[4][4], b[4][4];
            #pragma unroll
            for (int mi = 0; mi < 4; mi++)
                ldsm4(a[mi], As + a_sw[mi] + (cx ^ a_sx[mi]));
            #pragma unroll
            for (int g = 0; g < 4; g++)
                ldsm4(b[g], As + b_sw[g] + (cx ^ b_sx[g]));
            #pragma unroll
            for (int mi = 0; mi < 4; mi++)
                #pragma unroll
                for (int ni = 0; ni < 8; ni++)
                    mma_bf16(acc[mi][ni], a[mi],
                             b[ni >> 1][ni & 1], b[ni >> 1][(ni & 1) + 2]);
        }
    }

    // ---- epilogue: screened score = 2*xc - c2 + 1024, fp16 ----
    #pragma unroll
    for (int ni = 0; ni < 8; ni++) {
        int n0 = bn + wn * 64 + ni * 8 + 2 * (lane & 3);
        float c2a = 1024.f - g_c2[n0];
        float c2b = 1024.f - g_c2[n0 + 1];
        #pragma unroll
        for (int mi = 0; mi < 4; mi++) {
            int m0 = bm + wm * 64 + mi * 16 + (lane >> 2);
            __half2 h0 = __floats2half2_rn(2.f * acc[mi][ni][0] + c2a,
                                           2.f * acc[mi][ni][1] + c2b);
            *reinterpret_cast<__half2*>(&g_scores[(size_t)m0 * CDIM + n0]) = h0;
            __half2 h1 = __floats2half2_rn(2.f * acc[mi][ni][2] + c2a,
                                           2.f * acc[mi][ni][3] + c2b);
            *reinterpret_cast<__half2*>(&g_scores[(size_t)(m0 + 8) * CDIM + n0]) = h1;
        }
    }
}

// ---------------- kernel 3: select + exact fp64 rescore ----------------------
#define MARGIN 6.0f
#define MAXCAND 128

__global__ __launch_bounds__(256) void select_rescore(
    const float* __restrict__ x, const float* __restrict__ cb,
    float* __restrict__ out)
{
    __shared__ float  xs[KDIM];
    __shared__ float  smax[8];
    __shared__ double sred[2][8];
    __shared__ int    cand[MAXCAND];
    __shared__ int    ncand;

    const int m    = blockIdx.x;
    const int t    = threadIdx.x;
    const int lane = t & 31;
    const int wrp  = t >> 5;

    {
        const float4* src = reinterpret_cast<const float4*>(x + (size_t)m * KDIM);
        reinterpret_cast<float4*>(xs)[t] = src[t];
    }
    if (t == 0) ncand = 0;

    const uint4* row = reinterpret_cast<const uint4*>(g_scores + (size_t)m * CDIM);
    uint4 v[4];
    float lmax = -3.4e38f;
    #pragma unroll
    for (int j = 0; j < 4; j++) {
        v[j] = row[t + 256 * j];
        const __half2* h = reinterpret_cast<const __half2*>(&v[j]);
        #pragma unroll
        for (int e = 0; e < 4; e++) {
            float2 f = __half22float2(h[e]);
            lmax = fmaxf(lmax, fmaxf(f.x, f.y));
        }
    }
    #pragma unroll
    for (int o = 16; o; o >>= 1)
        lmax = fmaxf(lmax, __shfl_xor_sync(0xffffffffu, lmax, o));
    if (lane == 0) smax[wrp] = lmax;
    __syncthreads();
    float rowmax = smax[0];
    #pragma unroll
    for (int w = 1; w < 8; w++) rowmax = fmaxf(rowmax, smax[w]);
    const float thresh = rowmax - MARGIN;

    #pragma unroll
    for (int j = 0; j < 4; j++) {
        const __half2* h = reinterpret_cast<const __half2*>(&v[j]);
        #pragma unroll
        for (int e = 0; e < 4; e++) {
            float2 f = __half22float2(h[e]);
            int base = (t + 256 * j) * 8 + e * 2;
            if (f.x > thresh) { int p = atomicAdd(&ncand, 1); if (p < MAXCAND) cand[p] = base; }
            if (f.y > thresh) { int p = atomicAdd(&ncand, 1); if (p < MAXCAND) cand[p] = base + 1; }
        }
    }
    __syncthreads();
    int nc = min(ncand, MAXCAND);

    double bestS = -1e300;
    int    bestI = 0x7FFFFFFF;
    for (int ci = 0; ci < nc; ci++) {
        int c = cand[ci];
        const float* crow = cb + (size_t)c * KDIM;
        double s = 0.0, cc = 0.0;
        for (int d = t; d < KDIM; d += 256) {
            double cv = (double)crow[d];
            s  += (double)xs[d] * cv;
            cc += cv * cv;
        }
        #pragma unroll
        for (int o = 16; o; o >>= 1) {
            s  += __shfl_xor_sync(0xffffffffu, s,  o);
            cc += __shfl_xor_sync(0xffffffffu, cc, o);
        }
        if (lane == 0) { sred[0][wrp] = s; sred[1][wrp] = cc; }
        __syncthreads();
        double st = 0.0, ct = 0.0;
        #pragma unroll
        for (int w = 0; w < 8; w++) { st += sred[0][w]; ct += sred[1][w]; }
        __syncthreads();
        double sc = 2.0 * st - ct;
        if (sc > bestS || (sc == bestS && c < bestI)) { bestS = sc; bestI = c; }
    }

    const float4* src = reinterpret_cast<const float4*>(cb + (size_t)bestI * KDIM);
    float4* dst = reinterpret_cast<float4*>(out + (size_t)m * KDIM);
    dst[t] = src[t];
}

// ---------------- launch ------------------------------------------------------
extern "C" void kernel_launch(void* const* d_in, const int* in_sizes, int n_in,
                              void* d_out, int out_size)
{
    const float* x  = (const float*)d_in[0];   // [8192, 1024]
    const float* cb = (const float*)d_in[1];   // [8192, 1024]
    float* out = (float*)d_out;

    const int NX = MDIM * KDIM;
    const int NC = CDIM * KDIM;

    __nv_bfloat16 *xb_p = nullptr, *cb_p = nullptr;
    cudaGetSymbolAddress((void**)&xb_p, g_xb);
    cudaGetSymbolAddress((void**)&cb_p, g_cbb);

    cudaFuncSetAttribute(screen_gemm,
                         cudaFuncAttributeMaxDynamicSharedMemorySize,
                         NSTAGE * STAGE_BYTES);

    convert_kernel<<<NX / 1024, 256>>>(x,  xb_p, NX);
    convert_kernel<<<NC / 1024, 256>>>(cb, cb_p, NC);
    c2_kernel<<<CDIM / 8, 256>>>(cb, CDIM, KDIM);

    dim3 grid(CDIM / 128, MDIM / 128);
    screen_gemm<<<grid, 128, NSTAGE * STAGE_BYTES>>>();

    select_rescore<<<MDIM, 256>>>(x, cb, out);
}

// round 8
// speedup vs baseline: 1.5826x; 1.5826x over previous
#include <cuda_runtime.h>
#include <cuda_bf16.h>
#include <cuda_fp16.h>
#include <cstdint>

// ---------------------------------------------------------------------------
// CodebookLayer: out[m] = codebook[argmax_c (2*x.c - ||c||^2)]
//
// Round 8: R4 bf16 screen GEMM (256 thr, 8 warps 2x4, warp tile 64x32, BK=32)
// + fragment double-buffering (ldsm/mma overlap) + 4-stage cp.async (dist 3).
// Exact fp64 rescore of candidates within MARGIN of row max (unchanged).
// ---------------------------------------------------------------------------

#define MDIM 8192
#define CDIM 8192
#define KDIM 1024

__device__ __half        g_scores[(size_t)MDIM * CDIM];   // 128 MB scratch
__device__ __nv_bfloat16 g_xb [(size_t)MDIM * KDIM];
__device__ __nv_bfloat16 g_cbb[(size_t)CDIM * KDIM];
__device__ float         g_c2[CDIM];

// ---------------- helpers ---------------------------------------------------
__device__ __forceinline__ uint32_t smem_u32(const void* p) {
    uint32_t a;
    asm("{ .reg .u64 t; cvta.to.shared.u64 t, %1; cvt.u32.u64 %0, t; }"
        : "=r"(a) : "l"(p));
    return a;
}
__device__ __forceinline__ void cp16(uint32_t s, const void* g) {
    asm volatile("cp.async.cg.shared.global [%0], [%1], 16;"
                 :: "r"(s), "l"(g) : "memory");
}
__device__ __forceinline__ void ldsm4(uint32_t* r, uint32_t addr) {
    asm volatile("ldmatrix.sync.aligned.m8n8.x4.shared.b16 {%0,%1,%2,%3}, [%4];"
        : "=r"(r[0]), "=r"(r[1]), "=r"(r[2]), "=r"(r[3]) : "r"(addr));
}
__device__ __forceinline__ void mma_bf16(float* d, const uint32_t* a,
                                         uint32_t b0, uint32_t b1) {
    asm volatile(
        "mma.sync.aligned.m16n8k16.row.col.f32.bf16.bf16.f32 "
        "{%0,%1,%2,%3}, {%4,%5,%6,%7}, {%8,%9}, {%0,%1,%2,%3};"
        : "+f"(d[0]), "+f"(d[1]), "+f"(d[2]), "+f"(d[3])
        : "r"(a[0]), "r"(a[1]), "r"(a[2]), "r"(a[3]), "r"(b0), "r"(b1));
}

// ---------------- kernel 0: fp32 -> bf16 ------------------------------------
__global__ void convert_kernel(const float* __restrict__ s,
                               __nv_bfloat16* __restrict__ d, int n) {
    int i = (blockIdx.x * blockDim.x + threadIdx.x) * 4;
    if (i >= n) return;
    float4 v = *reinterpret_cast<const float4*>(s + i);
    __nv_bfloat162 p0 = {__float2bfloat16(v.x), __float2bfloat16(v.y)};
    __nv_bfloat162 p1 = {__float2bfloat16(v.z), __float2bfloat16(v.w)};
    *reinterpret_cast<__nv_bfloat162*>(d + i)     = p0;
    *reinterpret_cast<__nv_bfloat162*>(d + i + 2) = p1;
}

// ---------------- kernel 1: codebook row norms -------------------------------
__global__ void c2_kernel(const float* __restrict__ cb, int C, int K) {
    int row  = blockIdx.x * (blockDim.x >> 5) + (threadIdx.x >> 5);
    int lane = threadIdx.x & 31;
    if (row >= C) return;
    const float4* p = reinterpret_cast<const float4*>(cb + (size_t)row * K);
    float s = 0.f;
    for (int i = lane; i < (K >> 2); i += 32) {
        float4 v = p[i];
        s += v.x * v.x + v.y * v.y + v.z * v.z + v.w * v.w;
    }
    #pragma unroll
    for (int m = 16; m; m >>= 1) s += __shfl_xor_sync(0xffffffffu, s, m);
    if (lane == 0) g_c2[row] = s;
}

// ---------------- kernel 2: bf16 screening GEMM ------------------------------
// BM=BN=128, BK=32, 256 thr (8 warps 2x4), warp tile 64x32,
// 4-stage cp.async (prefetch distance 3), fragment double-buffering.
#define NSTAGE 4
#define STAGE_BYTES 16384          // A 8KB + B 8KB (128 rows x 64B)
#define NS (KDIM / 32)             // 32 k-stages

__global__ __launch_bounds__(256, 2) void screen_gemm() {
    extern __shared__ __align__(128) char smem[];   // 4 * 16 KB
    const uint32_t sb = smem_u32(smem);

    const int t    = threadIdx.x;
    const int lane = t & 31;
    const int wid  = t >> 5;
    const int wm   = wid >> 2;          // 0..1
    const int wn   = wid & 3;           // 0..3
    const int bm   = blockIdx.y * 128;
    const int bn   = blockIdx.x * 128;

    // ---- cp.async mapping (R4): thread t -> rows r0, r0+64, chunk ch ----
    const int r0 = t >> 2;              // 0..63
    const int ch = t & 3;
    const uint32_t sw   = (uint32_t)(ch ^ ((r0 >> 1) & 3)) << 4;
    const uint32_t wo0  = (uint32_t)r0 * 64 + sw;         // row r0
    const uint32_t wo1  = (uint32_t)(r0 + 64) * 64 + sw;  // row r0+64

    const __nv_bfloat16* pa0 = g_xb  + (size_t)(bm + r0)      * KDIM + ch * 8;
    const __nv_bfloat16* pa1 = g_xb  + (size_t)(bm + r0 + 64) * KDIM + ch * 8;
    const __nv_bfloat16* pb0 = g_cbb + (size_t)(bn + r0)      * KDIM + ch * 8;
    const __nv_bfloat16* pb1 = g_cbb + (size_t)(bn + r0 + 64) * KDIM + ch * 8;

    #define ISSUE_STAGE(so)                                                   \
        {                                                                     \
            cp16((so) + wo0,        pa0); cp16((so) + 8192 + wo0, pb0);       \
            cp16((so) + wo1,        pa1); cp16((so) + 8192 + wo1, pb1);       \
            pa0 += 32; pa1 += 32; pb0 += 32; pb1 += 32;                       \
        }

    // ---- ldmatrix bases (R4-proven swizzle) ----
    const int rbase = lane & 15;
    const uint32_t lh = (uint32_t)(lane >> 4);   // 0/1
    uint32_t a_off[4], a_x[4], b_off[2], b_x[2];
    #pragma unroll
    for (int mi = 0; mi < 4; mi++) {
        int row = wm * 64 + mi * 16 + rbase;
        a_off[mi] = (uint32_t)row * 64;
        a_x[mi]   = (uint32_t)((row >> 1) & 3);
    }
    #pragma unroll
    for (int g = 0; g < 2; g++) {
        int row = wn * 32 + g * 16 + rbase;
        b_off[g] = 8192u + (uint32_t)row * 64;
        b_x[g]   = (uint32_t)((row >> 1) & 3);
    }

    uint32_t af[2][4][4], bf[2][2][4];

    #define LOADK(pp, As, kk)                                                 \
        {                                                                     \
            uint32_t cin = (uint32_t)(2 * (kk)) | lh;                         \
            ldsm4(af[pp][0], (As) + a_off[0] + ((cin ^ a_x[0]) << 4));        \
            ldsm4(af[pp][1], (As) + a_off[1] + ((cin ^ a_x[1]) << 4));        \
            ldsm4(af[pp][2], (As) + a_off[2] + ((cin ^ a_x[2]) << 4));        \
            ldsm4(af[pp][3], (As) + a_off[3] + ((cin ^ a_x[3]) << 4));        \
            ldsm4(bf[pp][0], (As) + b_off[0] + ((cin ^ b_x[0]) << 4));        \
            ldsm4(bf[pp][1], (As) + b_off[1] + ((cin ^ b_x[1]) << 4));        \
        }

    #define MMAK(pp)                                                         \
        {                                                                    \
            _Pragma("unroll")                                                \
            for (int mi = 0; mi < 4; mi++)                                   \
                _Pragma("unroll")                                            \
                for (int ni = 0; ni < 4; ni++)                               \
                    mma_bf16(acc[mi][ni], af[pp][mi],                        \
                             bf[pp][ni >> 1][ni & 1],                        \
                             bf[pp][ni >> 1][(ni & 1) + 2]);                 \
        }

    float acc[4][4][4];
    #pragma unroll
    for (int i = 0; i < 4; i++)
        #pragma unroll
        for (int j = 0; j < 4; j++)
            #pragma unroll
            for (int k = 0; k < 4; k++) acc[i][j][k] = 0.f;

    // ---- prologue: stages 0..2, then make stage 0 resident ----
    #pragma unroll
    for (int s = 0; s < 3; s++) {
        ISSUE_STAGE(sb + s * STAGE_BYTES)
        asm volatile("cp.async.commit_group;" ::: "memory");
    }
    asm volatile("cp.async.wait_group 2;" ::: "memory");
    __syncthreads();
    LOADK(0, sb + 0 * STAGE_BYTES, 0)

    for (int s = 0; s < NS; s++) {
        const uint32_t As = sb + (s & (NSTAGE - 1)) * STAGE_BYTES;

        if (s + 3 < NS) { ISSUE_STAGE(sb + ((s + 3) & (NSTAGE - 1)) * STAGE_BYTES) }
        asm volatile("cp.async.commit_group;" ::: "memory");

        LOADK(1, As, 1)          // overlaps with MMAK(0) below
        MMAK(0)

        if (s + 1 < NS) {
            asm volatile("cp.async.wait_group 2;" ::: "memory");
            __syncthreads();     // stage s+1 resident; buf (s+3)&3 protected
            LOADK(0, sb + ((s + 1) & (NSTAGE - 1)) * STAGE_BYTES, 0)
        }
        MMAK(1)
    }

    // ---- epilogue: screened score = 2*xc - c2 + 1024, fp16 ----
    #pragma unroll
    for (int ni = 0; ni < 4; ni++) {
        int n0 = bn + wn * 32 + ni * 8 + 2 * (lane & 3);
        float c2a = 1024.f - g_c2[n0];
        float c2b = 1024.f - g_c2[n0 + 1];
        #pragma unroll
        for (int mi = 0; mi < 4; mi++) {
            int m0 = bm + wm * 64 + mi * 16 + (lane >> 2);
            __half2 h0 = __floats2half2_rn(2.f * acc[mi][ni][0] + c2a,
                                           2.f * acc[mi][ni][1] + c2b);
            *reinterpret_cast<__half2*>(&g_scores[(size_t)m0 * CDIM + n0]) = h0;
            __half2 h1 = __floats2half2_rn(2.f * acc[mi][ni][2] + c2a,
                                           2.f * acc[mi][ni][3] + c2b);
            *reinterpret_cast<__half2*>(&g_scores[(size_t)(m0 + 8) * CDIM + n0]) = h1;
        }
    }
}

// ---------------- kernel 3: select + exact fp64 rescore ----------------------
#define MARGIN 6.0f
#define MAXCAND 128

__global__ __launch_bounds__(256) void select_rescore(
    const float* __restrict__ x, const float* __restrict__ cb,
    float* __restrict__ out)
{
    __shared__ float  xs[KDIM];
    __shared__ float  smax[8];
    __shared__ double sred[2][8];
    __shared__ int    cand[MAXCAND];
    __shared__ int    ncand;

    const int m    = blockIdx.x;
    const int t    = threadIdx.x;
    const int lane = t & 31;
    const int wrp  = t >> 5;

    {
        const float4* src = reinterpret_cast<const float4*>(x + (size_t)m * KDIM);
        reinterpret_cast<float4*>(xs)[t] = src[t];
    }
    if (t == 0) ncand = 0;

    const uint4* row = reinterpret_cast<const uint4*>(g_scores + (size_t)m * CDIM);
    uint4 v[4];
    float lmax = -3.4e38f;
    #pragma unroll
    for (int j = 0; j < 4; j++) {
        v[j] = row[t + 256 * j];
        const __half2* h = reinterpret_cast<const __half2*>(&v[j]);
        #pragma unroll
        for (int e = 0; e < 4; e++) {
            float2 f = __half22float2(h[e]);
            lmax = fmaxf(lmax, fmaxf(f.x, f.y));
        }
    }
    #pragma unroll
    for (int o = 16; o; o >>= 1)
        lmax = fmaxf(lmax, __shfl_xor_sync(0xffffffffu, lmax, o));
    if (lane == 0) smax[wrp] = lmax;
    __syncthreads();
    float rowmax = smax[0];
    #pragma unroll
    for (int w = 1; w < 8; w++) rowmax = fmaxf(rowmax, smax[w]);
    const float thresh = rowmax - MARGIN;

    #pragma unroll
    for (int j = 0; j < 4; j++) {
        const __half2* h = reinterpret_cast<const __half2*>(&v[j]);
        #pragma unroll
        for (int e = 0; e < 4; e++) {
            float2 f = __half22float2(h[e]);
            int base = (t + 256 * j) * 8 + e * 2;
            if (f.x > thresh) { int p = atomicAdd(&ncand, 1); if (p < MAXCAND) cand[p] = base; }
            if (f.y > thresh) { int p = atomicAdd(&ncand, 1); if (p < MAXCAND) cand[p] = base + 1; }
        }
    }
    __syncthreads();
    int nc = min(ncand, MAXCAND);

    double bestS = -1e300;
    int    bestI = 0x7FFFFFFF;
    for (int ci = 0; ci < nc; ci++) {
        int c = cand[ci];
        const float* crow = cb + (size_t)c * KDIM;
        double s = 0.0, cc = 0.0;
        for (int d = t; d < KDIM; d += 256) {
            double cv = (double)crow[d];
            s  += (double)xs[d] * cv;
            cc += cv * cv;
        }
        #pragma unroll
        for (int o = 16; o; o >>= 1) {
            s  += __shfl_xor_sync(0xffffffffu, s,  o);
            cc += __shfl_xor_sync(0xffffffffu, cc, o);
        }
        if (lane == 0) { sred[0][wrp] = s; sred[1][wrp] = cc; }
        __syncthreads();
        double st = 0.0, ct = 0.0;
        #pragma unroll
        for (int w = 0; w < 8; w++) { st += sred[0][w]; ct += sred[1][w]; }
        __syncthreads();
        double sc = 2.0 * st - ct;
        if (sc > bestS || (sc == bestS && c < bestI)) { bestS = sc; bestI = c; }
    }

    const float4* src = reinterpret_cast<const float4*>(cb + (size_t)bestI * KDIM);
    float4* dst = reinterpret_cast<float4*>(out + (size_t)m * KDIM);
    dst[t] = src[t];
}

// ---------------- launch ------------------------------------------------------
extern "C" void kernel_launch(void* const* d_in, const int* in_sizes, int n_in,
                              void* d_out, int out_size)
{
    const float* x  = (const float*)d_in[0];   // [8192, 1024]
    const float* cb = (const float*)d_in[1];   // [8192, 1024]
    float* out = (float*)d_out;

    const int NX = MDIM * KDIM;
    const int NC = CDIM * KDIM;

    __nv_bfloat16 *xb_p = nullptr, *cb_p = nullptr;
    cudaGetSymbolAddress((void**)&xb_p, g_xb);
    cudaGetSymbolAddress((void**)&cb_p, g_cbb);

    cudaFuncSetAttribute(screen_gemm,
                         cudaFuncAttributeMaxDynamicSharedMemorySize,
                         NSTAGE * STAGE_BYTES);

    convert_kernel<<<NX / 1024, 256>>>(x,  xb_p, NX);
    convert_kernel<<<NC / 1024, 256>>>(cb, cb_p, NC);
    c2_kernel<<<CDIM / 8, 256>>>(cb, CDIM, KDIM);

    dim3 grid(CDIM / 128, MDIM / 128);
    screen_gemm<<<grid, 256, NSTAGE * STAGE_BYTES>>>();

    select_rescore<<<MDIM, 256>>>(x, cb, out);
}